// round 16
// baseline (speedup 1.0000x reference)
#include <cuda_runtime.h>
#include <math.h>
#include <math_constants.h>

// ---------------- problem constants ----------------
#define BATCH 256
#define CCH   16
#define TLEN  2000
#define NFFT  200
#define HOPL  100
#define NFREQ 101
#define NFP   104              // padded freq (stride, mult of 8, 16B aligned rows)
#define NFR   19               // (2000-200)/100+1
#define EMB   256
#define SEQ   (CCH*NFR)        // 304
#define MROWS (BATCH*SEQ)      // 77824
#define DEPTH 4
#define FF4   1024
#define NHEAD 8
#define DH    32
#define LNEPS 1e-5f

// ---------------- scratch (static device memory; no allocs allowed) ----------------
__device__ float g_dftc[NFFT*NFREQ];
__device__ float g_dfts[NFFT*NFREQ];
__device__ float g_projW[NFP*EMB];
__device__ float g_spec[(size_t)MROWS*NFP];
__device__ float g_y  [(size_t)MROWS*EMB];
__device__ float g_q  [(size_t)MROWS*EMB];
__device__ float g_k  [(size_t)MROWS*EMB];
__device__ float g_v  [(size_t)MROWS*EMB];
__device__ float g_ctx[(size_t)BATCH*NHEAD*DH*DH];
__device__ float g_ffn[(size_t)MROWS*FF4];

// ---------------- init: windowed DFT tables + padded projection ----------------
__global__ void init_tables_kernel() {
    int idx = blockIdx.x * blockDim.x + threadIdx.x;
    if (idx >= NFFT * NFREQ) return;
    int k = idx / NFREQ, f = idx % NFREQ;
    int m = (k * f) % NFFT;                       // exact angle reduction
    double ang = 2.0 * CUDART_PI * (double)m / (double)NFFT;
    double win = 0.5 * (1.0 - cos(2.0 * CUDART_PI * (double)k / (double)NFFT));
    g_dftc[idx] = (float)(cos(ang) * win);
    g_dfts[idx] = (float)(sin(ang) * win);
}

__global__ void pad_projW_kernel(const float* __restrict__ W) {
    int i = blockIdx.x * blockDim.x + threadIdx.x;
    if (i >= NFP * EMB) return;
    int r = i / EMB, c = i % EMB;
    g_projW[i] = (r < NFREQ) ? W[r * EMB + c] : 0.f;
}

// ---------------- STFT magnitude: one block per frame ----------------
__global__ void stft_kernel(const float* __restrict__ x) {
    __shared__ float xs[NFFT];
    int fr = blockIdx.x;                       // 0..MROWS-1  (= (b*C+c)*NFR + f)
    int bc = fr / NFR, f = fr % NFR;
    const float* xp = x + (size_t)bc * TLEN + f * HOPL;
    for (int i = threadIdx.x; i < NFFT; i += blockDim.x) xs[i] = xp[i];
    __syncthreads();
    int t = threadIdx.x;
    if (t < NFP) {
        float val = 0.f;
        if (t < NFREQ) {
            float re = 0.f, im = 0.f;
            #pragma unroll 8
            for (int k = 0; k < NFFT; k++) {
                float xv = xs[k];
                re += xv * g_dftc[k * NFREQ + t];
                im += xv * g_dfts[k * NFREQ + t];
            }
            val = sqrtf(re * re + im * im);
        }
        g_spec[(size_t)fr * NFP + t] = val;
    }
}

// ---------------- generic SGEMM: C = epi(A[M,K(lda)] @ W[K,N] + bias) ----------------
// EPI: 0 = bias only, 1 = gelu(·+bias), 2 = C += ·+bias (residual), 3 = emb epilogue
template <int EPI>
__global__ void __launch_bounds__(256)
gemm_kernel(const float* __restrict__ A, const float* __restrict__ W,
            const float* __restrict__ bias, float* __restrict__ C,
            int M, int N, int K, int lda,
            const float* __restrict__ chan_tok, const int* __restrict__ p_off)
{
    __shared__ float As[8][128];
    __shared__ float Bs[8][128];
    const int tid = threadIdx.x;
    const int tx = tid & 15, ty = tid >> 4;
    const int row0 = blockIdx.y * 128, col0 = blockIdx.x * 128;

    float acc[8][8];
    #pragma unroll
    for (int i = 0; i < 8; i++)
        #pragma unroll
        for (int j = 0; j < 8; j++) acc[i][j] = 0.f;

    const int ar = tid >> 1, ac = (tid & 1) * 4;       // A tile 128x8
    const int br = tid >> 5, bc = (tid & 31) * 4;      // B tile 8x128

    for (int k0 = 0; k0 < K; k0 += 8) {
        float4 av = *(const float4*)&A[(size_t)(row0 + ar) * lda + k0 + ac];
        As[ac + 0][ar] = av.x; As[ac + 1][ar] = av.y;
        As[ac + 2][ar] = av.z; As[ac + 3][ar] = av.w;
        *(float4*)&Bs[br][bc] = *(const float4*)&W[(size_t)(k0 + br) * N + col0 + bc];
        __syncthreads();
        #pragma unroll
        for (int kk = 0; kk < 8; kk++) {
            float4 a0 = *(const float4*)&As[kk][ty * 4];
            float4 a1 = *(const float4*)&As[kk][64 + ty * 4];
            float4 b0 = *(const float4*)&Bs[kk][tx * 4];
            float4 b1 = *(const float4*)&Bs[kk][64 + tx * 4];
            float a[8] = {a0.x, a0.y, a0.z, a0.w, a1.x, a1.y, a1.z, a1.w};
            float b[8] = {b0.x, b0.y, b0.z, b0.w, b1.x, b1.y, b1.z, b1.w};
            #pragma unroll
            for (int i = 0; i < 8; i++)
                #pragma unroll
                for (int j = 0; j < 8; j++) acc[i][j] += a[i] * b[j];
        }
        __syncthreads();
    }

    const int off = (EPI == 3 && p_off) ? *p_off : 0;
    #pragma unroll
    for (int i = 0; i < 8; i++) {
        int row = row0 + ((i < 4) ? (ty * 4 + i) : (64 + ty * 4 + i - 4));
        #pragma unroll
        for (int jh = 0; jh < 2; jh++) {
            int col = col0 + jh * 64 + tx * 4;
            float v[4];
            #pragma unroll
            for (int j = 0; j < 4; j++) v[j] = acc[i][jh * 4 + j];
            if (bias) {
                float4 bb = *(const float4*)&bias[col];
                v[0] += bb.x; v[1] += bb.y; v[2] += bb.z; v[3] += bb.w;
            }
            if (EPI == 1) {
                #pragma unroll
                for (int j = 0; j < 4; j++)
                    v[j] = 0.5f * v[j] * (1.f + erff(v[j] * 0.7071067811865475f));
            }
            if (EPI == 2) {
                float4 cc = *(const float4*)&C[(size_t)row * N + col];
                v[0] += cc.x; v[1] += cc.y; v[2] += cc.z; v[3] += cc.w;
            }
            if (EPI == 3) {
                int ch = (row / NFR) % CCH;
                int fpos = row % NFR;
                #pragma unroll
                for (int j = 0; j < 4; j++) {
                    int c = col + j;
                    v[j] += chan_tok[(off + ch) * EMB + c];
                    int p2 = (c >> 1) * 2;
                    float div = expf(-(float)p2 * (9.210340371976184f / (float)EMB));
                    float s, cth;
                    sincosf((float)fpos * div, &s, &cth);
                    v[j] += (c & 1) ? cth : s;
                }
            }
            float4 ov = {v[0], v[1], v[2], v[3]};
            *(float4*)&C[(size_t)row * N + col] = ov;
        }
    }
}

// ---------------- LayerNorm: one block (256 thr) per row ----------------
__global__ void ln_kernel(const float* __restrict__ h, const float* __restrict__ g,
                          const float* __restrict__ b, float* __restrict__ y) {
    __shared__ float red[256];
    int row = blockIdx.x, t = threadIdx.x;
    float x = h[(size_t)row * EMB + t];
    red[t] = x; __syncthreads();
    #pragma unroll
    for (int s = 128; s > 0; s >>= 1) { if (t < s) red[t] += red[t + s]; __syncthreads(); }
    float mu = red[0] * (1.f / EMB);
    __syncthreads();
    float d = x - mu;
    red[t] = d * d; __syncthreads();
    #pragma unroll
    for (int s = 128; s > 0; s >>= 1) { if (t < s) red[t] += red[t + s]; __syncthreads(); }
    float var = red[0] * (1.f / EMB);
    y[(size_t)row * EMB + t] = d * rsqrtf(var + LNEPS) * g[t] + b[t];
}

// ---------------- softmax over feature dim (per token-head, 32 elems) + scale ----------------
__global__ void softmax_q_kernel(float* __restrict__ q) {
    size_t gw = ((size_t)blockIdx.x * blockDim.x + threadIdx.x) >> 5;
    int lane = threadIdx.x & 31;
    if (gw >= (size_t)MROWS * NHEAD) return;
    size_t base = gw * DH;
    float v = q[base + lane];
    float m = v;
    #pragma unroll
    for (int o = 16; o > 0; o >>= 1) m = fmaxf(m, __shfl_xor_sync(0xffffffffu, m, o));
    float e = __expf(v - m);
    float s = e;
    #pragma unroll
    for (int o = 16; o > 0; o >>= 1) s += __shfl_xor_sync(0xffffffffu, s, o);
    q[base + lane] = e / s * 0.17677669529663687f;   // * dh^-0.5
}

// ---------------- softmax over sequence dim: block = (batch, 32-col tile) ----------------
__global__ void softmax_k_kernel(float* __restrict__ k) {
    __shared__ float red[32][33];
    int b = blockIdx.x;
    int e = blockIdx.y * 32 + threadIdx.x;
    int tx = threadIdx.x, ty = threadIdx.y;
    float vals[10];
    float m = -1e30f;
    #pragma unroll
    for (int i = 0; i < 10; i++) {
        int n = ty + i * 32;
        if (n < SEQ) { vals[i] = k[((size_t)b * SEQ + n) * EMB + e]; m = fmaxf(m, vals[i]); }
        else vals[i] = -1e30f;
    }
    red[ty][tx] = m; __syncthreads();
    if (ty == 0) { float mm = red[0][tx]; for (int i = 1; i < 32; i++) mm = fmaxf(mm, red[i][tx]); red[0][tx] = mm; }
    __syncthreads();
    m = red[0][tx];
    float s = 0.f;
    #pragma unroll
    for (int i = 0; i < 10; i++) {
        int n = ty + i * 32;
        if (n < SEQ) { vals[i] = __expf(vals[i] - m); s += vals[i]; }
    }
    __syncthreads();
    red[ty][tx] = s; __syncthreads();
    if (ty == 0) { float ss = 0.f; for (int i = 0; i < 32; i++) ss += red[i][tx]; red[0][tx] = ss; }
    __syncthreads();
    float inv = 1.f / red[0][tx];
    #pragma unroll
    for (int i = 0; i < 10; i++) {
        int n = ty + i * 32;
        if (n < SEQ) k[((size_t)b * SEQ + n) * EMB + e] = vals[i] * inv;
    }
}

// ---------------- ctx[b,h] = K_h^T @ V_h  (32x32 per block) ----------------
__global__ void ctx_kernel(const float* __restrict__ k, const float* __restrict__ v,
                           float* __restrict__ ctx) {
    __shared__ float ks[32][33], vs[32][33];
    int b = blockIdx.x, h = blockIdx.y;
    int tx = threadIdx.x, ty = threadIdx.y;
    float acc = 0.f;
    for (int n0 = 0; n0 < SEQ; n0 += 32) {
        int n = n0 + ty;
        float kv = 0.f, vv = 0.f;
        if (n < SEQ) {
            size_t base = ((size_t)b * SEQ + n) * EMB + h * DH;
            kv = k[base + tx]; vv = v[base + tx];
        }
        ks[ty][tx] = kv; vs[ty][tx] = vv;
        __syncthreads();
        #pragma unroll
        for (int nn = 0; nn < 32; nn++) acc += ks[nn][ty] * vs[nn][tx];
        __syncthreads();
    }
    ctx[(((size_t)b * NHEAD + h) * DH + ty) * DH + tx] = acc;
}

// ---------------- o = q @ ctx  (block: 16 tokens of one batch) ----------------
__global__ void o_kernel(const float* __restrict__ q, const float* __restrict__ ctx,
                         float* __restrict__ o) {
    __shared__ float cs[NHEAD * DH * DH];   // 32 KB
    __shared__ float qs[16][EMB];           // 16 KB
    int blk = blockIdx.x;
    int b = blk / (SEQ / 16);
    int t0 = (blk % (SEQ / 16)) * 16;
    int tid = threadIdx.x;
    for (int i = tid; i < NHEAD * DH * DH; i += 256)
        cs[i] = ctx[(size_t)b * NHEAD * DH * DH + i];
    size_t base = ((size_t)b * SEQ + t0) * EMB;
    for (int i = tid; i < 16 * EMB; i += 256)
        qs[i >> 8][i & 255] = q[base + i];
    __syncthreads();
    int e = tid, h = e >> 5, d = e & 31;
    const float* ch = &cs[h * DH * DH];
    #pragma unroll
    for (int t = 0; t < 16; t++) {
        float acc = 0.f;
        #pragma unroll
        for (int j = 0; j < 32; j++) acc += qs[t][h * 32 + j] * ch[j * DH + d];
        o[base + (size_t)t * EMB + e] = acc;
    }
}

// ---------------- mean over sequence ----------------
__global__ void mean_kernel(const float* __restrict__ h, float* __restrict__ out) {
    int b = blockIdx.x, e = threadIdx.x;
    float acc = 0.f;
    for (int n = 0; n < SEQ; n++) acc += h[((size_t)b * SEQ + n) * EMB + e];
    out[b * EMB + e] = acc * (1.f / SEQ);
}

// ---------------- host launcher ----------------
static float* symf(const void* s) { void* p = nullptr; cudaGetSymbolAddress(&p, s); return (float*)p; }

extern "C" void kernel_launch(void* const* d_in, const int* in_sizes, int n_in,
                              void* d_out, int out_size) {
    const float* x        = (const float*)d_in[0];
    const int*   p_off    = (const int*)  d_in[1];
    const float* proj_W   = (const float*)d_in[2];
    const float* proj_b   = (const float*)d_in[3];
    const float* chan_tok = (const float*)d_in[4];
    const float* Wq = (const float*)d_in[5];
    const float* Wk = (const float*)d_in[6];
    const float* Wv = (const float*)d_in[7];
    const float* Wo = (const float*)d_in[8];
    const float* bo = (const float*)d_in[9];
    const float* ln1_g = (const float*)d_in[10];
    const float* ln1_b = (const float*)d_in[11];
    const float* ln2_g = (const float*)d_in[12];
    const float* ln2_b = (const float*)d_in[13];
    const float* W1 = (const float*)d_in[14];
    const float* b1 = (const float*)d_in[15];
    const float* W2 = (const float*)d_in[16];
    const float* b2 = (const float*)d_in[17];

    float* out_mean = (float*)d_out;
    float* h = out_mean + (size_t)BATCH * EMB;     // h lives in d_out directly

    float* spec = symf(g_spec);
    float* projWp = symf(g_projW);
    float* yb  = symf(g_y);
    float* qb  = symf(g_q);
    float* kb  = symf(g_k);
    float* vb  = symf(g_v);
    float* ctxb = symf(g_ctx);
    float* ffnb = symf(g_ffn);

    // init tables (cheap, deterministic every call)
    init_tables_kernel<<<(NFFT * NFREQ + 255) / 256, 256>>>();
    pad_projW_kernel<<<(NFP * EMB + 255) / 256, 256>>>(proj_W);

    // STFT magnitude
    stft_kernel<<<MROWS, 128>>>(x);

    // emb = spec @ proj_W + proj_b + chan_tok + pe  -> h
    dim3 thr(256);
    dim3 g_emb(EMB / 128, MROWS / 128);
    gemm_kernel<3><<<g_emb, thr>>>(spec, projWp, proj_b, h, MROWS, EMB, NFP, NFP,
                                   chan_tok, p_off);

    dim3 gE(EMB / 128, MROWS / 128);
    dim3 gF(FF4 / 128, MROWS / 128);
    dim3 smk_grid(BATCH, EMB / 32), bh_grid(BATCH, NHEAD);
    dim3 b32(32, 32);

    for (int l = 0; l < DEPTH; l++) {
        const float* wq = Wq + (size_t)l * EMB * EMB;
        const float* wk = Wk + (size_t)l * EMB * EMB;
        const float* wv = Wv + (size_t)l * EMB * EMB;
        const float* wo = Wo + (size_t)l * EMB * EMB;
        const float* w1 = W1 + (size_t)l * EMB * FF4;
        const float* w2 = W2 + (size_t)l * FF4 * EMB;

        ln_kernel<<<MROWS, 256>>>(h, ln1_g + l * EMB, ln1_b + l * EMB, yb);
        gemm_kernel<0><<<gE, thr>>>(yb, wq, nullptr, qb, MROWS, EMB, EMB, EMB, nullptr, nullptr);
        gemm_kernel<0><<<gE, thr>>>(yb, wk, nullptr, kb, MROWS, EMB, EMB, EMB, nullptr, nullptr);
        gemm_kernel<0><<<gE, thr>>>(yb, wv, nullptr, vb, MROWS, EMB, EMB, EMB, nullptr, nullptr);

        softmax_q_kernel<<<MROWS, 256>>>(qb);
        softmax_k_kernel<<<smk_grid, b32>>>(kb);
        ctx_kernel<<<bh_grid, b32>>>(kb, vb, ctxb);
        o_kernel<<<BATCH * (SEQ / 16), 256>>>(qb, ctxb, yb);

        gemm_kernel<2><<<gE, thr>>>(yb, wo, bo + l * EMB, h, MROWS, EMB, EMB, EMB, nullptr, nullptr);

        ln_kernel<<<MROWS, 256>>>(h, ln2_g + l * EMB, ln2_b + l * EMB, yb);
        gemm_kernel<1><<<gF, thr>>>(yb, w1, b1 + l * FF4, ffnb, MROWS, FF4, EMB, EMB, nullptr, nullptr);
        gemm_kernel<2><<<gE, thr>>>(ffnb, w2, b2 + l * EMB, h, MROWS, EMB, FF4, FF4, nullptr, nullptr);
    }

    mean_kernel<<<BATCH, 256>>>(h, out_mean);
}

// round 17
// speedup vs baseline: 1.0035x; 1.0035x over previous
#include <cuda_runtime.h>
#include <math.h>
#include <math_constants.h>

// ---------------- problem constants ----------------
#define BATCH 256
#define CCH   16
#define TLEN  2000
#define NFFT  200
#define HOPL  100
#define NFREQ 101
#define NFP   104              // padded freq (stride, mult of 8, 16B aligned rows)
#define NFR   19               // (2000-200)/100+1
#define EMB   256
#define SEQ   (CCH*NFR)        // 304
#define MROWS (BATCH*SEQ)      // 77824
#define DEPTH 4
#define FF4   1024
#define NHEAD 8
#define DH    32
#define LNEPS 1e-5f

// ---------------- scratch (static device memory; no allocs allowed) ----------------
__device__ float g_dftc[NFFT*NFREQ];
__device__ float g_dfts[NFFT*NFREQ];
__device__ float g_projW[NFP*EMB];
__device__ float g_spec[(size_t)MROWS*NFP];
__device__ float g_y  [(size_t)MROWS*EMB];
__device__ float g_q  [(size_t)MROWS*EMB];
__device__ float g_k  [(size_t)MROWS*EMB];
__device__ float g_v  [(size_t)MROWS*EMB];
__device__ float g_ctx[(size_t)BATCH*NHEAD*DH*DH];
__device__ float g_ffn[(size_t)MROWS*FF4];

// ---------------- init: windowed DFT tables + padded projection ----------------
__global__ void init_tables_kernel() {
    int idx = blockIdx.x * blockDim.x + threadIdx.x;
    if (idx >= NFFT * NFREQ) return;
    int k = idx / NFREQ, f = idx % NFREQ;
    int m = (k * f) % NFFT;                       // exact angle reduction
    double ang = 2.0 * CUDART_PI * (double)m / (double)NFFT;
    double win = 0.5 * (1.0 - cos(2.0 * CUDART_PI * (double)k / (double)NFFT));
    g_dftc[idx] = (float)(cos(ang) * win);
    g_dfts[idx] = (float)(sin(ang) * win);
}

__global__ void pad_projW_kernel(const float* __restrict__ W) {
    int i = blockIdx.x * blockDim.x + threadIdx.x;
    if (i >= NFP * EMB) return;
    int r = i / EMB, c = i % EMB;
    g_projW[i] = (r < NFREQ) ? W[r * EMB + c] : 0.f;
}

// ---------------- STFT magnitude: one block per frame ----------------
__global__ void stft_kernel(const float* __restrict__ x) {
    __shared__ float xs[NFFT];
    int fr = blockIdx.x;                       // 0..MROWS-1  (= (b*C+c)*NFR + f)
    int bc = fr / NFR, f = fr % NFR;
    const float* xp = x + (size_t)bc * TLEN + f * HOPL;
    for (int i = threadIdx.x; i < NFFT; i += blockDim.x) xs[i] = xp[i];
    __syncthreads();
    int t = threadIdx.x;
    if (t < NFP) {
        float val = 0.f;
        if (t < NFREQ) {
            float re = 0.f, im = 0.f;
            #pragma unroll 8
            for (int k = 0; k < NFFT; k++) {
                float xv = xs[k];
                re += xv * g_dftc[k * NFREQ + t];
                im += xv * g_dfts[k * NFREQ + t];
            }
            val = sqrtf(re * re + im * im);
        }
        g_spec[(size_t)fr * NFP + t] = val;
    }
}

// ---------------- generic SGEMM: C = epi(A[M,K(lda)] @ W[K,N] + bias) ----------------
// EPI: 0 = bias only, 1 = gelu(·+bias), 2 = C += ·+bias (residual), 3 = emb epilogue
template <int EPI>
__global__ void __launch_bounds__(256)
gemm_kernel(const float* __restrict__ A, const float* __restrict__ W,
            const float* __restrict__ bias, float* __restrict__ C,
            int M, int N, int K, int lda,
            const float* __restrict__ chan_tok, const int* __restrict__ p_off)
{
    __shared__ float As[8][128];
    __shared__ float Bs[8][128];
    const int tid = threadIdx.x;
    const int tx = tid & 15, ty = tid >> 4;
    const int row0 = blockIdx.y * 128, col0 = blockIdx.x * 128;

    float acc[8][8];
    #pragma unroll
    for (int i = 0; i < 8; i++)
        #pragma unroll
        for (int j = 0; j < 8; j++) acc[i][j] = 0.f;

    const int ar = tid >> 1, ac = (tid & 1) * 4;       // A tile 128x8
    const int br = tid >> 5, bc = (tid & 31) * 4;      // B tile 8x128

    for (int k0 = 0; k0 < K; k0 += 8) {
        float4 av = *(const float4*)&A[(size_t)(row0 + ar) * lda + k0 + ac];
        As[ac + 0][ar] = av.x; As[ac + 1][ar] = av.y;
        As[ac + 2][ar] = av.z; As[ac + 3][ar] = av.w;
        *(float4*)&Bs[br][bc] = *(const float4*)&W[(size_t)(k0 + br) * N + col0 + bc];
        __syncthreads();
        #pragma unroll
        for (int kk = 0; kk < 8; kk++) {
            float4 a0 = *(const float4*)&As[kk][ty * 4];
            float4 a1 = *(const float4*)&As[kk][64 + ty * 4];
            float4 b0 = *(const float4*)&Bs[kk][tx * 4];
            float4 b1 = *(const float4*)&Bs[kk][64 + tx * 4];
            float a[8] = {a0.x, a0.y, a0.z, a0.w, a1.x, a1.y, a1.z, a1.w};
            float b[8] = {b0.x, b0.y, b0.z, b0.w, b1.x, b1.y, b1.z, b1.w};
            #pragma unroll
            for (int i = 0; i < 8; i++)
                #pragma unroll
                for (int j = 0; j < 8; j++) acc[i][j] += a[i] * b[j];
        }
        __syncthreads();
    }

    const int off = (EPI == 3 && p_off) ? *p_off : 0;
    #pragma unroll
    for (int i = 0; i < 8; i++) {
        int row = row0 + ((i < 4) ? (ty * 4 + i) : (64 + ty * 4 + i - 4));
        #pragma unroll
        for (int jh = 0; jh < 2; jh++) {
            int col = col0 + jh * 64 + tx * 4;
            float v[4];
            #pragma unroll
            for (int j = 0; j < 4; j++) v[j] = acc[i][jh * 4 + j];
            if (bias) {
                float4 bb = *(const float4*)&bias[col];
                v[0] += bb.x; v[1] += bb.y; v[2] += bb.z; v[3] += bb.w;
            }
            if (EPI == 1) {
                #pragma unroll
                for (int j = 0; j < 4; j++)
                    v[j] = 0.5f * v[j] * (1.f + erff(v[j] * 0.7071067811865475f));
            }
            if (EPI == 2) {
                float4 cc = *(const float4*)&C[(size_t)row * N + col];
                v[0] += cc.x; v[1] += cc.y; v[2] += cc.z; v[3] += cc.w;
            }
            if (EPI == 3) {
                int ch = (row / NFR) % CCH;
                int fpos = row % NFR;
                #pragma unroll
                for (int j = 0; j < 4; j++) {
                    int c = col + j;
                    v[j] += chan_tok[(off + ch) * EMB + c];
                    int p2 = (c >> 1) * 2;
                    float div = expf(-(float)p2 * (9.210340371976184f / (float)EMB));
                    float s, cth;
                    sincosf((float)fpos * div, &s, &cth);
                    v[j] += (c & 1) ? cth : s;
                }
            }
            float4 ov = {v[0], v[1], v[2], v[3]};
            *(float4*)&C[(size_t)row * N + col] = ov;
        }
    }
}

// ---------------- LayerNorm: one block (256 thr) per row ----------------
__global__ void ln_kernel(const float* __restrict__ h, const float* __restrict__ g,
                          const float* __restrict__ b, float* __restrict__ y) {
    __shared__ float red[256];
    int row = blockIdx.x, t = threadIdx.x;
    float x = h[(size_t)row * EMB + t];
    red[t] = x; __syncthreads();
    #pragma unroll
    for (int s = 128; s > 0; s >>= 1) { if (t < s) red[t] += red[t + s]; __syncthreads(); }
    float mu = red[0] * (1.f / EMB);
    __syncthreads();
    float d = x - mu;
    red[t] = d * d; __syncthreads();
    #pragma unroll
    for (int s = 128; s > 0; s >>= 1) { if (t < s) red[t] += red[t + s]; __syncthreads(); }
    float var = red[0] * (1.f / EMB);
    y[(size_t)row * EMB + t] = d * rsqrtf(var + LNEPS) * g[t] + b[t];
}

// ---------------- softmax over feature dim (per token-head, 32 elems) + scale ----------------
__global__ void softmax_q_kernel(float* __restrict__ q) {
    size_t gw = ((size_t)blockIdx.x * blockDim.x + threadIdx.x) >> 5;
    int lane = threadIdx.x & 31;
    if (gw >= (size_t)MROWS * NHEAD) return;
    size_t base = gw * DH;
    float v = q[base + lane];
    float m = v;
    #pragma unroll
    for (int o = 16; o > 0; o >>= 1) m = fmaxf(m, __shfl_xor_sync(0xffffffffu, m, o));
    float e = __expf(v - m);
    float s = e;
    #pragma unroll
    for (int o = 16; o > 0; o >>= 1) s += __shfl_xor_sync(0xffffffffu, s, o);
    q[base + lane] = e / s * 0.17677669529663687f;   // * dh^-0.5
}

// ---------------- softmax over sequence dim: block = (batch, 32-col tile) ----------------
__global__ void softmax_k_kernel(float* __restrict__ k) {
    __shared__ float red[32][33];
    int b = blockIdx.x;
    int e = blockIdx.y * 32 + threadIdx.x;
    int tx = threadIdx.x, ty = threadIdx.y;
    float vals[10];
    float m = -1e30f;
    #pragma unroll
    for (int i = 0; i < 10; i++) {
        int n = ty + i * 32;
        if (n < SEQ) { vals[i] = k[((size_t)b * SEQ + n) * EMB + e]; m = fmaxf(m, vals[i]); }
        else vals[i] = -1e30f;
    }
    red[ty][tx] = m; __syncthreads();
    if (ty == 0) { float mm = red[0][tx]; for (int i = 1; i < 32; i++) mm = fmaxf(mm, red[i][tx]); red[0][tx] = mm; }
    __syncthreads();
    m = red[0][tx];
    float s = 0.f;
    #pragma unroll
    for (int i = 0; i < 10; i++) {
        int n = ty + i * 32;
        if (n < SEQ) { vals[i] = __expf(vals[i] - m); s += vals[i]; }
    }
    __syncthreads();
    red[ty][tx] = s; __syncthreads();
    if (ty == 0) { float ss = 0.f; for (int i = 0; i < 32; i++) ss += red[i][tx]; red[0][tx] = ss; }
    __syncthreads();
    float inv = 1.f / red[0][tx];
    #pragma unroll
    for (int i = 0; i < 10; i++) {
        int n = ty + i * 32;
        if (n < SEQ) k[((size_t)b * SEQ + n) * EMB + e] = vals[i] * inv;
    }
}

// ---------------- ctx[b,h] = K_h^T @ V_h  (32x32 per block) ----------------
__global__ void ctx_kernel(const float* __restrict__ k, const float* __restrict__ v,
                           float* __restrict__ ctx) {
    __shared__ float ks[32][33], vs[32][33];
    int b = blockIdx.x, h = blockIdx.y;
    int tx = threadIdx.x, ty = threadIdx.y;
    float acc = 0.f;
    for (int n0 = 0; n0 < SEQ; n0 += 32) {
        int n = n0 + ty;
        float kv = 0.f, vv = 0.f;
        if (n < SEQ) {
            size_t base = ((size_t)b * SEQ + n) * EMB + h * DH;
            kv = k[base + tx]; vv = v[base + tx];
        }
        ks[ty][tx] = kv; vs[ty][tx] = vv;
        __syncthreads();
        #pragma unroll
        for (int nn = 0; nn < 32; nn++) acc += ks[nn][ty] * vs[nn][tx];
        __syncthreads();
    }
    ctx[(((size_t)b * NHEAD + h) * DH + ty) * DH + tx] = acc;
}

// ---------------- o = q @ ctx  (block: 16 tokens of one batch) ----------------
__global__ void o_kernel(const float* __restrict__ q, const float* __restrict__ ctx,
                         float* __restrict__ o) {
    __shared__ float cs[NHEAD * DH * DH];   // 32 KB
    __shared__ float qs[16][EMB];           // 16 KB
    int blk = blockIdx.x;
    int b = blk / (SEQ / 16);
    int t0 = (blk % (SEQ / 16)) * 16;
    int tid = threadIdx.x;
    for (int i = tid; i < NHEAD * DH * DH; i += 256)
        cs[i] = ctx[(size_t)b * NHEAD * DH * DH + i];
    size_t base = ((size_t)b * SEQ + t0) * EMB;
    for (int i = tid; i < 16 * EMB; i += 256)
        qs[i >> 8][i & 255] = q[base + i];
    __syncthreads();
    int e = tid, h = e >> 5, d = e & 31;
    const float* ch = &cs[h * DH * DH];
    #pragma unroll
    for (int t = 0; t < 16; t++) {
        float acc = 0.f;
        #pragma unroll
        for (int j = 0; j < 32; j++) acc += qs[t][h * 32 + j] * ch[j * DH + d];
        o[base + (size_t)t * EMB + e] = acc;
    }
}

// ---------------- mean over sequence ----------------
__global__ void mean_kernel(const float* __restrict__ h, float* __restrict__ out) {
    int b = blockIdx.x, e = threadIdx.x;
    float acc = 0.f;
    for (int n = 0; n < SEQ; n++) acc += h[((size_t)b * SEQ + n) * EMB + e];
    out[b * EMB + e] = acc * (1.f / SEQ);
}

// ---------------- host launcher ----------------
static float* symf(const void* s) { void* p = nullptr; cudaGetSymbolAddress(&p, s); return (float*)p; }

extern "C" void kernel_launch(void* const* d_in, const int* in_sizes, int n_in,
                              void* d_out, int out_size) {
    const float* x        = (const float*)d_in[0];
    const int*   p_off    = (const int*)  d_in[1];
    const float* proj_W   = (const float*)d_in[2];
    const float* proj_b   = (const float*)d_in[3];
    const float* chan_tok = (const float*)d_in[4];
    const float* Wq = (const float*)d_in[5];
    const float* Wk = (const float*)d_in[6];
    const float* Wv = (const float*)d_in[7];
    const float* Wo = (const float*)d_in[8];
    const float* bo = (const float*)d_in[9];
    const float* ln1_g = (const float*)d_in[10];
    const float* ln1_b = (const float*)d_in[11];
    const float* ln2_g = (const float*)d_in[12];
    const float* ln2_b = (const float*)d_in[13];
    const float* W1 = (const float*)d_in[14];
    const float* b1 = (const float*)d_in[15];
    const float* W2 = (const float*)d_in[16];
    const float* b2 = (const float*)d_in[17];

    float* out_mean = (float*)d_out;
    float* h = out_mean + (size_t)BATCH * EMB;     // h lives in d_out directly

    float* spec = symf(g_spec);
    float* projWp = symf(g_projW);
    float* yb  = symf(g_y);
    float* qb  = symf(g_q);
    float* kb  = symf(g_k);
    float* vb  = symf(g_v);
    float* ctxb = symf(g_ctx);
    float* ffnb = symf(g_ffn);

    // init tables (cheap, deterministic every call)
    init_tables_kernel<<<(NFFT * NFREQ + 255) / 256, 256>>>();
    pad_projW_kernel<<<(NFP * EMB + 255) / 256, 256>>>(proj_W);

    // STFT magnitude
    stft_kernel<<<MROWS, 128>>>(x);

    // emb = spec @ proj_W + proj_b + chan_tok + pe  -> h
    dim3 thr(256);
    dim3 g_emb(EMB / 128, MROWS / 128);
    gemm_kernel<3><<<g_emb, thr>>>(spec, projWp, proj_b, h, MROWS, EMB, NFP, NFP,
                                   chan_tok, p_off);

    dim3 gE(EMB / 128, MROWS / 128);
    dim3 gF(FF4 / 128, MROWS / 128);
    dim3 smk_grid(BATCH, EMB / 32), bh_grid(BATCH, NHEAD);
    dim3 b32(32, 32);

    for (int l = 0; l < DEPTH; l++) {
        const float* wq = Wq + (size_t)l * EMB * EMB;
        const float* wk = Wk + (size_t)l * EMB * EMB;
        const float* wv = Wv + (size_t)l * EMB * EMB;
        const float* wo = Wo + (size_t)l * EMB * EMB;
        const float* w1 = W1 + (size_t)l * EMB * FF4;
        const float* w2 = W2 + (size_t)l * FF4 * EMB;

        ln_kernel<<<MROWS, 256>>>(h, ln1_g + l * EMB, ln1_b + l * EMB, yb);
        gemm_kernel<0><<<gE, thr>>>(yb, wq, nullptr, qb, MROWS, EMB, EMB, EMB, nullptr, nullptr);
        gemm_kernel<0><<<gE, thr>>>(yb, wk, nullptr, kb, MROWS, EMB, EMB, EMB, nullptr, nullptr);
        gemm_kernel<0><<<gE, thr>>>(yb, wv, nullptr, vb, MROWS, EMB, EMB, EMB, nullptr, nullptr);

        softmax_q_kernel<<<MROWS, 256>>>(qb);
        softmax_k_kernel<<<smk_grid, b32>>>(kb);
        ctx_kernel<<<bh_grid, b32>>>(kb, vb, ctxb);
        o_kernel<<<BATCH * (SEQ / 16), 256>>>(qb, ctxb, yb);

        gemm_kernel<2><<<gE, thr>>>(yb, wo, bo + l * EMB, h, MROWS, EMB, EMB, EMB, nullptr, nullptr);

        ln_kernel<<<MROWS, 256>>>(h, ln2_g + l * EMB, ln2_b + l * EMB, yb);
        gemm_kernel<1><<<gF, thr>>>(yb, w1, b1 + l * FF4, ffnb, MROWS, FF4, EMB, EMB, nullptr, nullptr);
        gemm_kernel<2><<<gE, thr>>>(ffnb, w2, b2 + l * EMB, h, MROWS, EMB, FF4, FF4, nullptr, nullptr);
    }

    mean_kernel<<<BATCH, 256>>>(h, out_mean);
}